// round 5
// baseline (speedup 1.0000x reference)
#include <cuda_runtime.h>

// Problem: tet geometry + vertex segment-max.
// Inputs:  d_in[0] vertices  (V=1,000,000 x 3 f32)
//          d_in[1] indices   (T=4,000,000 x 4 i32)
//          d_in[2] tet_density (T f32)
// Output:  d_out = [tet_area (T) | tet_alpha (T) | vert_density (V)] f32
//
// Model (validated R2-R3): tet kernel is pinned at the joint L1-wavefront /
// L2-transaction floor (16M divergent gather sectors + 16M spread RED.MAX +
// ~3.6M streaming sectors). R4 attacks the remaining prep/launch edge:
//  - vd zero moved to cudaMemsetAsync (fill path, off the SM)
//  - copy kernel slimmed: 2 groups (8 verts) per thread, default cache policy

#define MAX_VERTS 1000000

__device__ float4 g_verts4[MAX_VERTS];

// Pad vertices to float4. Each thread: 8 vertices = 6 coalesced float4 loads,
// 8 float4 stores.
__global__ __launch_bounds__(256) void prep_kernel(const float4* __restrict__ verts4,
                                                   int num_pairs) {  // num_verts/8
    int p = blockIdx.x * blockDim.x + threadIdx.x;
    if (p >= num_pairs) return;

    int g = 2 * p;  // group of 4 verts; process g and g+1
    float4 a = verts4[3 * g + 0];
    float4 b = verts4[3 * g + 1];
    float4 c = verts4[3 * g + 2];
    float4 a2 = verts4[3 * g + 3];
    float4 b2 = verts4[3 * g + 4];
    float4 c2 = verts4[3 * g + 5];

    g_verts4[4 * g + 0] = make_float4(a.x, a.y, a.z, 0.0f);
    g_verts4[4 * g + 1] = make_float4(a.w, b.x, b.y, 0.0f);
    g_verts4[4 * g + 2] = make_float4(b.z, b.w, c.x, 0.0f);
    g_verts4[4 * g + 3] = make_float4(c.y, c.z, c.w, 0.0f);
    g_verts4[4 * g + 4] = make_float4(a2.x, a2.y, a2.z, 0.0f);
    g_verts4[4 * g + 5] = make_float4(a2.w, b2.x, b2.y, 0.0f);
    g_verts4[4 * g + 6] = make_float4(b2.z, b2.w, c2.x, 0.0f);
    g_verts4[4 * g + 7] = make_float4(c2.y, c2.z, c2.w, 0.0f);
}

__global__ __launch_bounds__(256) void tet_kernel(
        const int4* __restrict__ indices,
        const float* __restrict__ tet_density,
        float* __restrict__ tet_area,
        float* __restrict__ tet_alpha,
        int* __restrict__ vert_density_i,  // float bits, all >= 0
        int num_tets) {
    int t = blockIdx.x * blockDim.x + threadIdx.x;
    if (t >= num_tets) return;

    int4 idx = __ldcs(&indices[t]);      // streaming: evict-first
    float d  = __ldcs(&tet_density[t]);  // streaming: evict-first

    // 4 independent 16B gathers -> high MLP, 1 L2 sector each; default policy
    // so vertex lines stay resident in L2.
    float4 v0 = g_verts4[idx.x];
    float4 v1 = g_verts4[idx.y];
    float4 v2 = g_verts4[idx.z];
    float4 v3 = g_verts4[idx.w];

    // det of edge matrix
    float e1x = v1.x - v0.x, e1y = v1.y - v0.y, e1z = v1.z - v0.z;
    float e2x = v2.x - v0.x, e2y = v2.y - v0.y, e2z = v2.z - v0.z;
    float e3x = v3.x - v0.x, e3y = v3.y - v0.y, e3z = v3.z - v0.z;

    float det = e1x * (e2y * e3z - e2z * e3y)
              - e1y * (e2x * e3z - e2z * e3x)
              + e1z * (e2x * e3y - e2y * e3x);
    float area = fabsf(det) * (1.0f / 6.0f);

    // min squared edge length over all 6 edges
    float d01 = e1x * e1x + e1y * e1y + e1z * e1z;
    float d02 = e2x * e2x + e2y * e2y + e2z * e2z;
    float d03 = e3x * e3x + e3y * e3y + e3z * e3z;
    float ax = v1.x - v2.x, ay = v1.y - v2.y, az = v1.z - v2.z;
    float d12 = ax * ax + ay * ay + az * az;
    float bx = v1.x - v3.x, by = v1.y - v3.y, bz = v1.z - v3.z;
    float d13 = bx * bx + by * by + bz * bz;
    float cx = v2.x - v3.x, cy = v2.y - v3.y, cz = v2.z - v3.z;
    float d23 = cx * cx + cy * cy + cz * cz;

    float m = fminf(fminf(fminf(d01, d02), fminf(d03, d12)), fminf(d13, d23));
    float el = sqrtf(m);
    float alpha = 1.0f - __expf(-d * el);

    __stcs(&tet_area[t], area);    // streaming store: evict-first
    __stcs(&tet_alpha[t], alpha);  // streaming store: evict-first

    // vertex segment-max. d >= 0 so int-bit atomicMax == float max (init 0).
    int db = __float_as_int(d);
    atomicMax(&vert_density_i[idx.x], db);
    atomicMax(&vert_density_i[idx.y], db);
    atomicMax(&vert_density_i[idx.z], db);
    atomicMax(&vert_density_i[idx.w], db);
}

extern "C" void kernel_launch(void* const* d_in, const int* in_sizes, int n_in,
                              void* d_out, int out_size) {
    const float* vertices    = (const float*)d_in[0];
    const int4*  indices     = (const int4*)d_in[1];
    const float* tet_density = (const float*)d_in[2];

    int num_verts = in_sizes[0] / 3;     // 1,000,000
    int num_tets  = in_sizes[2];         // 4,000,000
    if (num_verts > MAX_VERTS) num_verts = MAX_VERTS;  // fixed-shape problem

    float* out = (float*)d_out;
    float* tet_area     = out;
    float* tet_alpha    = out + (size_t)num_tets;
    float* vert_density = out + 2 * (size_t)num_tets;

    // Zero vert_density via the async fill path (graph-capturable).
    cudaMemsetAsync(vert_density, 0, (size_t)num_verts * sizeof(float));

    // num_verts = 1M is divisible by 8.
    int num_pairs = num_verts / 8;
    prep_kernel<<<(num_pairs + 255) / 256, 256>>>((const float4*)vertices, num_pairs);

    int threads = 256;
    int blocks = (num_tets + threads - 1) / threads;
    tet_kernel<<<blocks, threads>>>(indices, tet_density,
                                    tet_area, tet_alpha,
                                    (int*)vert_density, num_tets);
}

// round 6
// speedup vs baseline: 1.0007x; 1.0007x over previous
#include <cuda_runtime.h>

// Problem: tet geometry + vertex segment-max.
// Inputs:  d_in[0] vertices  (V=1,000,000 x 3 f32)
//          d_in[1] indices   (T=4,000,000 x 4 i32)
//          d_in[2] tet_density (T f32)
// Output:  d_out = [tet_area (T) | tet_alpha (T) | vert_density (V)] f32
//
// Model (validated R2-R4): tet kernel is pinned at the joint L1-wavefront /
// L2-transaction floor (16M divergent gather sectors + 16M spread RED.MAX).
// R5: best-known structure (R3) with prep edge squeezed:
//  - vd zeroing fused back into prep (memset node regressed R4 by ~3us)
//  - 8 verts/thread prep: 6 coalesced float4 loads, 8 stores + 2 vd-zero stores

#define MAX_VERTS 1000000

__device__ float4 g_verts4[MAX_VERTS];

// Pad vertices to float4 AND zero the vert_density output region.
__global__ __launch_bounds__(256) void prep_kernel(const float4* __restrict__ verts4,
                                                   float4* __restrict__ vd4,
                                                   int num_octets) {  // num_verts/8
    int p = blockIdx.x * blockDim.x + threadIdx.x;
    if (p >= num_octets) return;

    int g = 2 * p;  // two groups of 4 verts
    float4 a  = verts4[3 * g + 0];
    float4 b  = verts4[3 * g + 1];
    float4 c  = verts4[3 * g + 2];
    float4 a2 = verts4[3 * g + 3];
    float4 b2 = verts4[3 * g + 4];
    float4 c2 = verts4[3 * g + 5];

    g_verts4[4 * g + 0] = make_float4(a.x,  a.y,  a.z,  0.0f);
    g_verts4[4 * g + 1] = make_float4(a.w,  b.x,  b.y,  0.0f);
    g_verts4[4 * g + 2] = make_float4(b.z,  b.w,  c.x,  0.0f);
    g_verts4[4 * g + 3] = make_float4(c.y,  c.z,  c.w,  0.0f);
    g_verts4[4 * g + 4] = make_float4(a2.x, a2.y, a2.z, 0.0f);
    g_verts4[4 * g + 5] = make_float4(a2.w, b2.x, b2.y, 0.0f);
    g_verts4[4 * g + 6] = make_float4(b2.z, b2.w, c2.x, 0.0f);
    g_verts4[4 * g + 7] = make_float4(c2.y, c2.z, c2.w, 0.0f);

    float4 z = make_float4(0.0f, 0.0f, 0.0f, 0.0f);
    __stcs(&vd4[2 * p + 0], z);
    __stcs(&vd4[2 * p + 1], z);
}

__global__ __launch_bounds__(256) void tet_kernel(
        const int4* __restrict__ indices,
        const float* __restrict__ tet_density,
        float* __restrict__ tet_area,
        float* __restrict__ tet_alpha,
        int* __restrict__ vert_density_i,  // float bits, all >= 0
        int num_tets) {
    int t = blockIdx.x * blockDim.x + threadIdx.x;
    if (t >= num_tets) return;

    int4 idx = __ldcs(&indices[t]);      // streaming: evict-first
    float d  = __ldcs(&tet_density[t]);  // streaming: evict-first

    // 4 independent 16B gathers -> high MLP, 1 L2 sector each; default policy
    // so vertex lines stay resident in L2.
    float4 v0 = g_verts4[idx.x];
    float4 v1 = g_verts4[idx.y];
    float4 v2 = g_verts4[idx.z];
    float4 v3 = g_verts4[idx.w];

    // det of edge matrix
    float e1x = v1.x - v0.x, e1y = v1.y - v0.y, e1z = v1.z - v0.z;
    float e2x = v2.x - v0.x, e2y = v2.y - v0.y, e2z = v2.z - v0.z;
    float e3x = v3.x - v0.x, e3y = v3.y - v0.y, e3z = v3.z - v0.z;

    float det = e1x * (e2y * e3z - e2z * e3y)
              - e1y * (e2x * e3z - e2z * e3x)
              + e1z * (e2x * e3y - e2y * e3x);
    float area = fabsf(det) * (1.0f / 6.0f);

    // min squared edge length over all 6 edges
    float d01 = e1x * e1x + e1y * e1y + e1z * e1z;
    float d02 = e2x * e2x + e2y * e2y + e2z * e2z;
    float d03 = e3x * e3x + e3y * e3y + e3z * e3z;
    float ax = v1.x - v2.x, ay = v1.y - v2.y, az = v1.z - v2.z;
    float d12 = ax * ax + ay * ay + az * az;
    float bx = v1.x - v3.x, by = v1.y - v3.y, bz = v1.z - v3.z;
    float d13 = bx * bx + by * by + bz * bz;
    float cx = v2.x - v3.x, cy = v2.y - v3.y, cz = v2.z - v3.z;
    float d23 = cx * cx + cy * cy + cz * cz;

    float m = fminf(fminf(fminf(d01, d02), fminf(d03, d12)), fminf(d13, d23));
    float el = sqrtf(m);
    float alpha = 1.0f - __expf(-d * el);

    __stcs(&tet_area[t], area);    // streaming store: evict-first
    __stcs(&tet_alpha[t], alpha);  // streaming store: evict-first

    // vertex segment-max. d >= 0 so int-bit atomicMax == float max (init 0).
    int db = __float_as_int(d);
    atomicMax(&vert_density_i[idx.x], db);
    atomicMax(&vert_density_i[idx.y], db);
    atomicMax(&vert_density_i[idx.z], db);
    atomicMax(&vert_density_i[idx.w], db);
}

extern "C" void kernel_launch(void* const* d_in, const int* in_sizes, int n_in,
                              void* d_out, int out_size) {
    const float* vertices    = (const float*)d_in[0];
    const int4*  indices     = (const int4*)d_in[1];
    const float* tet_density = (const float*)d_in[2];

    int num_verts = in_sizes[0] / 3;     // 1,000,000
    int num_tets  = in_sizes[2];         // 4,000,000
    if (num_verts > MAX_VERTS) num_verts = MAX_VERTS;  // fixed-shape problem

    float* out = (float*)d_out;
    float* tet_area     = out;
    float* tet_alpha    = out + (size_t)num_tets;
    float* vert_density = out + 2 * (size_t)num_tets;

    // num_verts = 1M is divisible by 8; vd offset (8M floats) is 16B-aligned.
    int num_octets = num_verts / 8;
    prep_kernel<<<(num_octets + 255) / 256, 256>>>(
        (const float4*)vertices, (float4*)vert_density, num_octets);

    int threads = 256;
    int blocks = (num_tets + threads - 1) / threads;
    tet_kernel<<<blocks, threads>>>(indices, tet_density,
                                    tet_area, tet_alpha,
                                    (int*)vert_density, num_tets);
}

// round 7
// speedup vs baseline: 1.0203x; 1.0195x over previous
#include <cuda_runtime.h>

// Problem: tet geometry + vertex segment-max.
// Inputs:  d_in[0] vertices  (V=1,000,000 x 3 f32)
//          d_in[1] indices   (T=4,000,000 x 4 i32)
//          d_in[2] tet_density (T f32)
// Output:  d_out = [tet_area (T) | tet_alpha (T) | vert_density (V)] f32
//
// Model (validated R2-R5): tet kernel is pinned at the L2/L1 transaction-count
// floor: 16M divergent 16B gather sectors + 16M spread RED.MAX + ~4M streaming
// transactions vs ~184 LTS slices -> ~120us. Rejected on analysis: smaller
// vertex records (count-bound, not byte-bound), L1-filtered atomics (adds
// more transactions than it removes), index dedup (random indices),
// cooperative prep+tet fusion (grid.sync eats the saved launch).
// R6 = measured-best R3 structure + 512-thread tet blocks (halved CTA count).

#define MAX_VERTS 1000000

__device__ float4 g_verts4[MAX_VERTS];

// Prep: pad vertices to float4 AND zero the vert_density output region.
// Each thread: 4 vertices = 3 coalesced float4 loads, 4 float4 stores, 1 zero.
__global__ __launch_bounds__(256) void prep_kernel(const float4* __restrict__ verts4,
                                                   float4* __restrict__ vd4,
                                                   int num_groups) {  // num_verts/4
    int g = blockIdx.x * blockDim.x + threadIdx.x;
    if (g >= num_groups) return;

    float4 a = verts4[3 * g + 0];  // v0.x v0.y v0.z v1.x
    float4 b = verts4[3 * g + 1];  // v1.y v1.z v2.x v2.y
    float4 c = verts4[3 * g + 2];  // v2.z v3.x v3.y v3.z

    g_verts4[4 * g + 0] = make_float4(a.x, a.y, a.z, 0.0f);
    g_verts4[4 * g + 1] = make_float4(a.w, b.x, b.y, 0.0f);
    g_verts4[4 * g + 2] = make_float4(b.z, b.w, c.x, 0.0f);
    g_verts4[4 * g + 3] = make_float4(c.y, c.z, c.w, 0.0f);

    __stcs(&vd4[g], make_float4(0.0f, 0.0f, 0.0f, 0.0f));
}

__global__ __launch_bounds__(512) void tet_kernel(
        const int4* __restrict__ indices,
        const float* __restrict__ tet_density,
        float* __restrict__ tet_area,
        float* __restrict__ tet_alpha,
        int* __restrict__ vert_density_i,  // float bits, all >= 0
        int num_tets) {
    int t = blockIdx.x * blockDim.x + threadIdx.x;
    if (t >= num_tets) return;

    int4 idx = __ldcs(&indices[t]);      // streaming: evict-first
    float d  = __ldcs(&tet_density[t]);  // streaming: evict-first

    // 4 independent 16B gathers -> high MLP, 1 L2 sector each; default policy
    // so vertex lines stay resident in L2.
    float4 v0 = g_verts4[idx.x];
    float4 v1 = g_verts4[idx.y];
    float4 v2 = g_verts4[idx.z];
    float4 v3 = g_verts4[idx.w];

    // det of edge matrix
    float e1x = v1.x - v0.x, e1y = v1.y - v0.y, e1z = v1.z - v0.z;
    float e2x = v2.x - v0.x, e2y = v2.y - v0.y, e2z = v2.z - v0.z;
    float e3x = v3.x - v0.x, e3y = v3.y - v0.y, e3z = v3.z - v0.z;

    float det = e1x * (e2y * e3z - e2z * e3y)
              - e1y * (e2x * e3z - e2z * e3x)
              + e1z * (e2x * e3y - e2y * e3x);
    float area = fabsf(det) * (1.0f / 6.0f);

    // min squared edge length over all 6 edges
    float d01 = e1x * e1x + e1y * e1y + e1z * e1z;
    float d02 = e2x * e2x + e2y * e2y + e2z * e2z;
    float d03 = e3x * e3x + e3y * e3y + e3z * e3z;
    float ax = v1.x - v2.x, ay = v1.y - v2.y, az = v1.z - v2.z;
    float d12 = ax * ax + ay * ay + az * az;
    float bx = v1.x - v3.x, by = v1.y - v3.y, bz = v1.z - v3.z;
    float d13 = bx * bx + by * by + bz * bz;
    float cx = v2.x - v3.x, cy = v2.y - v3.y, cz = v2.z - v3.z;
    float d23 = cx * cx + cy * cy + cz * cz;

    float m = fminf(fminf(fminf(d01, d02), fminf(d03, d12)), fminf(d13, d23));
    float el = sqrtf(m);
    float alpha = 1.0f - __expf(-d * el);

    __stcs(&tet_area[t], area);    // streaming store: evict-first
    __stcs(&tet_alpha[t], alpha);  // streaming store: evict-first

    // vertex segment-max. d >= 0 so int-bit atomicMax == float max (init 0).
    int db = __float_as_int(d);
    atomicMax(&vert_density_i[idx.x], db);
    atomicMax(&vert_density_i[idx.y], db);
    atomicMax(&vert_density_i[idx.z], db);
    atomicMax(&vert_density_i[idx.w], db);
}

extern "C" void kernel_launch(void* const* d_in, const int* in_sizes, int n_in,
                              void* d_out, int out_size) {
    const float* vertices    = (const float*)d_in[0];
    const int4*  indices     = (const int4*)d_in[1];
    const float* tet_density = (const float*)d_in[2];

    int num_verts = in_sizes[0] / 3;     // 1,000,000
    int num_tets  = in_sizes[2];         // 4,000,000
    if (num_verts > MAX_VERTS) num_verts = MAX_VERTS;  // fixed-shape problem

    float* out = (float*)d_out;
    float* tet_area     = out;
    float* tet_alpha    = out + (size_t)num_tets;
    float* vert_density = out + 2 * (size_t)num_tets;

    // num_verts = 1M is divisible by 4; vd offset (8M floats) is 16B-aligned.
    int num_groups = num_verts / 4;
    prep_kernel<<<(num_groups + 255) / 256, 256>>>(
        (const float4*)vertices, (float4*)vert_density, num_groups);

    int threads = 512;
    int blocks = (num_tets + threads - 1) / threads;
    tet_kernel<<<blocks, threads>>>(indices, tet_density,
                                    tet_area, tet_alpha,
                                    (int*)vert_density, num_tets);
}